// round 2
// baseline (speedup 1.0000x reference)
#include <cuda_runtime.h>
#include <cuda_bf16.h>
#include <cstdint>
#include <cstddef>

#define BATCH 32
#define TT    1024
#define II    512
#define HH    512
#define G3    1536
#define NCTA_PER_DIR 32
#define NCTA_TOTAL   64

// ---------------- device scratch ----------------
__device__ float d_xn[(size_t)BATCH * TT * II];                 // LN output (tf32-rounded), [b][t][i]
__device__ float d_xp[(size_t)2 * TT * G3 * BATCH];             // x-projections, [dir][t][g][b]
__device__ float d_wihr[2 * G3 * II];                           // tf32 W_ih [dir][g][i]
__device__ float d_whp[2 * NCTA_PER_DIR * 48 * II];             // permuted tf32 W_hh [dir][c][j][k]
__device__ float d_h[2 * 2 * BATCH * HH];                       // h double buffer [dir][buf][b][h]
__device__ unsigned int d_bar;

// ---------------- helpers ----------------
__device__ __forceinline__ float tf32r(float x) {
    uint32_t u; asm("cvt.rna.tf32.f32 %0, %1;" : "=r"(u) : "f"(x));
    return __uint_as_float(u);
}
__device__ __forceinline__ void cp16(void* smem_dst, const void* gmem_src) {
    uint32_t s = (uint32_t)__cvta_generic_to_shared(smem_dst);
    asm volatile("cp.async.cg.shared.global [%0], [%1], 16;" :: "r"(s), "l"(gmem_src));
}
__device__ __forceinline__ void cp_commit() { asm volatile("cp.async.commit_group;"); }
template <int N> __device__ __forceinline__ void cp_wait() {
    asm volatile("cp.async.wait_group %0;" :: "n"(N));
}
__device__ __forceinline__ void mma_tf32(float* d, const uint32_t* a, const uint32_t* b) {
    asm volatile(
        "mma.sync.aligned.m16n8k8.row.col.f32.tf32.tf32.f32 "
        "{%0,%1,%2,%3},{%4,%5,%6,%7},{%8,%9},{%0,%1,%2,%3};"
        : "+f"(d[0]), "+f"(d[1]), "+f"(d[2]), "+f"(d[3])
        : "r"(a[0]), "r"(a[1]), "r"(a[2]), "r"(a[3]), "r"(b[0]), "r"(b[1]));
}
__device__ __forceinline__ int gate_row(int c, int j) {
    return (j < 16) ? (c * 16 + j)
         : (j < 32) ? (512 + c * 16 + (j - 16))
                    : (1024 + c * 16 + (j - 32));
}

// ---------------- kernel 0: prep ----------------
__global__ void prep_kernel(const float* __restrict__ wihf, const float* __restrict__ whhf,
                            const float* __restrict__ wihb, const float* __restrict__ whhb) {
    int idx = blockIdx.x * blockDim.x + threadIdx.x;
    int stride = gridDim.x * blockDim.x;
    for (int i = idx; i < 2 * G3 * II; i += stride) {
        int dir = i / (G3 * II);
        int r = i - dir * (G3 * II);
        d_wihr[i] = tf32r((dir ? wihb : wihf)[r]);
    }
    for (int i = idx; i < 2 * NCTA_PER_DIR * 48 * II; i += stride) {
        int k = i & (II - 1);
        int j = (i >> 9) % 48;
        int c = (i / (48 * II)) % NCTA_PER_DIR;
        int dir = i / (NCTA_PER_DIR * 48 * II);
        int g = gate_row(c, j);
        d_whp[i] = tf32r((dir ? whhb : whhf)[g * II + k]);
    }
    for (int i = idx; i < 2 * 2 * BATCH * HH; i += stride) d_h[i] = 0.0f;
    if (idx == 0) d_bar = 0u;
}

// ---------------- kernel 1: LayerNorm ----------------
__global__ void ln_kernel(const float* __restrict__ x, const float* __restrict__ gamma,
                          const float* __restrict__ beta) {
    int row = blockIdx.x;
    const float* xr = x + (size_t)row * II;
    int tid = threadIdx.x;
    float v[4]; float s = 0.f, q = 0.f;
#pragma unroll
    for (int k = 0; k < 4; k++) {
        v[k] = xr[tid + 128 * k];
        s += v[k]; q += v[k] * v[k];
    }
#pragma unroll
    for (int o = 16; o > 0; o >>= 1) {
        s += __shfl_xor_sync(0xffffffffu, s, o);
        q += __shfl_xor_sync(0xffffffffu, q, o);
    }
    __shared__ float ws[4], wq[4];
    if ((tid & 31) == 0) { ws[tid >> 5] = s; wq[tid >> 5] = q; }
    __syncthreads();
    s = ws[0] + ws[1] + ws[2] + ws[3];
    q = wq[0] + wq[1] + wq[2] + wq[3];
    float mu = s * (1.0f / 512.0f);
    float var = q * (1.0f / 512.0f) - mu * mu;
    float rstd = rsqrtf(var + 1e-5f);
#pragma unroll
    for (int k = 0; k < 4; k++) {
        int i = tid + 128 * k;
        d_xn[(size_t)row * II + i] = tf32r((v[k] - mu) * rstd * gamma[i] + beta[i]);
    }
}

// ---------------- kernel 2: input-projection GEMM ----------------
#define GEMM_BUF_FLOATS (128 * 36)
__global__ void __launch_bounds__(256)
gemm_kernel(const float* __restrict__ bihf, const float* __restrict__ bihb) {
    extern __shared__ float smem[];
    float* As = smem;                          // 2 * 128*36
    float* Bs = smem + 2 * GEMM_BUF_FLOATS;    // 2 * 128*36
    int bx = blockIdx.x, by = blockIdx.y, dir = blockIdx.z;
    int tid = threadIdx.x, lane = tid & 31, wid = tid >> 5;
    int wm = wid & 1, wn = wid >> 1;
    const float* bih = dir ? bihb : bihf;
    const float* Abase = d_wihr + (size_t)dir * G3 * II + (size_t)(by * 128) * II;

    auto load_tiles = [&](int kb, int buf) {
        float* As_ = As + buf * GEMM_BUF_FLOATS;
        float* Bs_ = Bs + buf * GEMM_BUF_FLOATS;
#pragma unroll
        for (int u = 0; u < 4; u++) {
            int o = tid + 256 * u;
            int row = o >> 3, seg = o & 7;
            cp16(&As_[row * 36 + seg * 4], Abase + (size_t)row * II + kb * 32 + seg * 4);
        }
#pragma unroll
        for (int u = 0; u < 4; u++) {
            int o = tid + 256 * u;
            int col = o >> 3, seg = o & 7;
            int n = bx * 128 + col;
            int t = n >> 5, b = n & 31;
            cp16(&Bs_[col * 36 + seg * 4], d_xn + ((size_t)b * TT + t) * II + kb * 32 + seg * 4);
        }
    };

    float acc[4][4][4];
#pragma unroll
    for (int i = 0; i < 4; i++)
#pragma unroll
        for (int j = 0; j < 4; j++)
#pragma unroll
            for (int k = 0; k < 4; k++) acc[i][j][k] = 0.f;

    load_tiles(0, 0); cp_commit();
    for (int kb = 0; kb < 16; kb++) {
        if (kb + 1 < 16) { load_tiles(kb + 1, (kb + 1) & 1); cp_commit(); cp_wait<1>(); }
        else cp_wait<0>();
        __syncthreads();
        float* As_ = As + (kb & 1) * GEMM_BUF_FLOATS;
        float* Bs_ = Bs + (kb & 1) * GEMM_BUF_FLOATS;
#pragma unroll
        for (int ks = 0; ks < 4; ks++) {
            int k0 = ks * 8 + (lane & 3);
            uint32_t af[4][4], bf[4][2];
#pragma unroll
            for (int mi = 0; mi < 4; mi++) {
                int r0 = wm * 64 + mi * 16 + (lane >> 2);
                af[mi][0] = __float_as_uint(As_[r0 * 36 + k0]);
                af[mi][1] = __float_as_uint(As_[(r0 + 8) * 36 + k0]);
                af[mi][2] = __float_as_uint(As_[r0 * 36 + k0 + 4]);
                af[mi][3] = __float_as_uint(As_[(r0 + 8) * 36 + k0 + 4]);
            }
#pragma unroll
            for (int ni = 0; ni < 4; ni++) {
                int c0 = wn * 32 + ni * 8 + (lane >> 2);
                bf[ni][0] = __float_as_uint(Bs_[c0 * 36 + k0]);
                bf[ni][1] = __float_as_uint(Bs_[c0 * 36 + k0 + 4]);
            }
#pragma unroll
            for (int mi = 0; mi < 4; mi++)
#pragma unroll
                for (int ni = 0; ni < 4; ni++) mma_tf32(acc[mi][ni], af[mi], bf[ni]);
        }
        __syncthreads();
    }
#pragma unroll
    for (int mi = 0; mi < 4; mi++)
#pragma unroll
        for (int ni = 0; ni < 4; ni++)
#pragma unroll
            for (int rr = 0; rr < 2; rr++) {
                int g = by * 128 + wm * 64 + mi * 16 + (lane >> 2) + rr * 8;
                int cb = bx * 128 + wn * 32 + ni * 8 + 2 * (lane & 3);
                int t = cb >> 5, b = cb & 31;
                float bias = bih[g];
                size_t off = ((size_t)dir * TT + t) * (size_t)(G3 * BATCH) + (size_t)g * BATCH + b;
                float2 v;
                v.x = acc[mi][ni][rr * 2 + 0] + bias;
                v.y = acc[mi][ni][rr * 2 + 1] + bias;
                *reinterpret_cast<float2*>(d_xp + off) = v;
            }
}

// ---------------- kernel 3: persistent recurrence ----------------
#define PADK 516
#define REC_SW_FLOATS  (48 * PADK)
#define REC_SB_FLOATS  (32 * PADK)
#define REC_XP_FLOATS  (48 * 32)
#define REC_SMEM_BYTES ((REC_SW_FLOATS + REC_SB_FLOATS + REC_XP_FLOATS + 64) * 4)

__global__ void __launch_bounds__(128, 1)
rec_kernel(const float* __restrict__ bhhf, const float* __restrict__ bhhb,
           float* __restrict__ out) {
    extern __shared__ float sm[];
    float* sW    = sm;                         // [48][PADK]
    float* sB    = sW + REC_SW_FLOATS;         // [32][PADK] (h per batch col, K-major)
    float* sXp   = sB + REC_SB_FLOATS;         // [48][32]
    float* sBias = sXp + REC_XP_FLOATS;        // [48]

    int c = blockIdx.x, dir = blockIdx.y;
    int tid = threadIdx.x, lane = tid & 31, warp = tid >> 5;
    int c16 = c * 16;

    {
        const float* src = d_whp + ((size_t)(dir * NCTA_PER_DIR + c)) * 48 * II;
        for (int i = tid; i < 48 * II; i += 128) {
            int j = i >> 9, k = i & (II - 1);
            sW[j * PADK + k] = src[i];
        }
        const float* bhh = dir ? bhhb : bhhf;
        if (tid < 48) sBias[tid] = bhh[gate_row(c, tid)];
    }
    __syncthreads();

    float* hbase = d_h + (size_t)dir * 2 * BATCH * HH;

    for (int s = 0; s < TT; s++) {
        int t = dir ? (TT - 1 - s) : s;
        const float* hrd = hbase + (size_t)(s & 1) * BATCH * HH;
        float* hwr = hbase + (size_t)((s + 1) & 1) * BATCH * HH;

        // issue async loads: 4 h K-chunks + xp slice (5 groups)
#pragma unroll
        for (int ch = 0; ch < 4; ch++) {
#pragma unroll
            for (int rep = 0; rep < 8; rep++) {
                int o = tid + 128 * rep;
                int col = o >> 5, seg = o & 31;
                cp16(&sB[col * PADK + ch * 128 + seg * 4],
                     hrd + col * HH + ch * 128 + seg * 4);
            }
            cp_commit();
        }
        {
            const float* xps = d_xp + ((size_t)dir * TT + t) * (size_t)(G3 * BATCH);
#pragma unroll
            for (int rep = 0; rep < 3; rep++) {
                int o = tid + 128 * rep;
                int j = o >> 3, seg = o & 7;
                int g = gate_row(c, j);
                cp16(&sXp[j * 32 + seg * 4], xps + (size_t)g * BATCH + seg * 4);
            }
            cp_commit();
        }

        float acc[3][4];
#pragma unroll
        for (int m = 0; m < 3; m++)
#pragma unroll
            for (int j = 0; j < 4; j++) acc[m][j] = 0.f;

#pragma unroll
        for (int kc = 0; kc < 4; kc++) {
            if (kc == 0) cp_wait<4>();
            else if (kc == 1) cp_wait<3>();
            else if (kc == 2) cp_wait<2>();
            else cp_wait<1>();
            __syncthreads();
#pragma unroll
            for (int kk = 0; kk < 16; kk++) {
                int k0 = kc * 128 + kk * 8 + (lane & 3);
                int r = lane >> 2;
                uint32_t bfr[2];
                bfr[0] = __float_as_uint(sB[(warp * 8 + r) * PADK + k0]);
                bfr[1] = __float_as_uint(sB[(warp * 8 + r) * PADK + k0 + 4]);
#pragma unroll
                for (int mi = 0; mi < 3; mi++) {
                    int row = mi * 16 + r;
                    uint32_t af[4];
                    af[0] = __float_as_uint(sW[row * PADK + k0]);
                    af[1] = __float_as_uint(sW[(row + 8) * PADK + k0]);
                    af[2] = __float_as_uint(sW[row * PADK + k0 + 4]);
                    af[3] = __float_as_uint(sW[(row + 8) * PADK + k0 + 4]);
                    mma_tf32(acc[mi], af, bfr);
                }
            }
        }

        cp_wait<0>();
        __syncthreads();

        // gates + h update + GELU output (register-local across the 3 m-tiles)
#pragma unroll
        for (int rr = 0; rr < 2; rr++)
#pragma unroll
            for (int cc = 0; cc < 2; cc++) {
                int row = (lane >> 2) + rr * 8;            // 0..15
                int b = warp * 8 + 2 * (lane & 3) + cc;    // 0..31
                int idx = rr * 2 + cc;
                float rpre = acc[0][idx] + sBias[row];
                float zpre = acc[1][idx] + sBias[16 + row];
                float npre = acc[2][idx] + sBias[32 + row];
                float xr = sXp[row * 32 + b];
                float xz = sXp[(16 + row) * 32 + b];
                float xnv = sXp[(32 + row) * 32 + b];
                float rg = 1.0f / (1.0f + __expf(-(xr + rpre)));
                float zg = 1.0f / (1.0f + __expf(-(xz + zpre)));
                float ng = tanhf(xnv + rg * npre);
                float hold = sB[b * PADK + c16 + row];
                float hnew = (1.0f - zg) * ng + zg * hold;
                hwr[b * HH + c16 + row] = hnew;
                float g = 0.5f * hnew * (1.0f + erff(hnew * 0.70710678118f));
                out[((size_t)b * TT + t) * (size_t)(2 * HH) + (size_t)dir * HH + c16 + row] = g;
            }

        // grid barrier (monotonic counter)
        __syncthreads();
        if (tid == 0) {
            __threadfence();
            atomicAdd(&d_bar, 1u);
            unsigned int target = (unsigned int)NCTA_TOTAL * (unsigned int)(s + 1);
            while (atomicAdd(&d_bar, 0u) < target) { }
            __threadfence();
        }
        __syncthreads();
    }
}

// ---------------- launcher ----------------
extern "C" void kernel_launch(void* const* d_in, const int* in_sizes, int n_in,
                              void* d_out, int out_size) {
    const float* x       = (const float*)d_in[0];
    const float* ln_g    = (const float*)d_in[1];
    const float* ln_b    = (const float*)d_in[2];
    const float* w_ih_f  = (const float*)d_in[3];
    const float* w_hh_f  = (const float*)d_in[4];
    const float* b_ih_f  = (const float*)d_in[5];
    const float* b_hh_f  = (const float*)d_in[6];
    const float* w_ih_b  = (const float*)d_in[7];
    const float* w_hh_b  = (const float*)d_in[8];
    const float* b_ih_b  = (const float*)d_in[9];
    const float* b_hh_b  = (const float*)d_in[10];
    float* out = (float*)d_out;

    static bool attr_done = false;
    if (!attr_done) {
        cudaFuncSetAttribute(gemm_kernel, cudaFuncAttributeMaxDynamicSharedMemorySize,
                             4 * GEMM_BUF_FLOATS * 4);
        cudaFuncSetAttribute(rec_kernel, cudaFuncAttributeMaxDynamicSharedMemorySize,
                             REC_SMEM_BYTES);
        attr_done = true;
    }

    prep_kernel<<<2048, 256>>>(w_ih_f, w_hh_f, w_ih_b, w_hh_b);
    ln_kernel<<<BATCH * TT, 128>>>(x, ln_g, ln_b);
    gemm_kernel<<<dim3(256, 12, 2), 256, 4 * GEMM_BUF_FLOATS * 4>>>(b_ih_f, b_ih_b);
    rec_kernel<<<dim3(NCTA_PER_DIR, 2), 128, REC_SMEM_BYTES>>>(b_hh_f, b_hh_b, out);
}